// round 17
// baseline (speedup 1.0000x reference)
#include <cuda_runtime.h>
#include <math.h>
#include <cstdint>

// ---------------- problem constants ----------------
#define T 2048
#define HIDDEN 2048
#define NH 32
#define NKV 4
#define D 128
#define WINDOW 512
#define QKV_W ((NH + 2*NKV) * D)   // 5120
#define ATT_SCALE 0.08838834764831845f
#define EPS 1e-6f

// K-dim layouts feeding the two GEMMs are PERMUTED within each 8-group:
// logical k -> physical (k<4 ? 2k : 2k-7), i.e. [0,4,1,5,2,6,3,7] stored order.
// Writers: cvt32 (hidden), transpose_cvt (weights), attn epilogue (g_ao).
// Reader: GEMM fragment loads (float2 at 2*tg).

// ---------------- device scratch (124 MB) ----------------
__device__ __align__(16) float g_qn [T * NH * D];     // 32 MB tf32 q
__device__ __align__(16) float g_kn [T * NKV * D];    //  4 MB tf32 k
__device__ __align__(16) float g_ao [T * NH * D];     // 32 MB: tf32 hidden (early) / attn out (late), K-permuted
__device__ __align__(16) float g_vt [NKV * D * T];    // 16 MB tf32 V^T [kvh][d][t]
__device__ __align__(16) float g_wT [QKV_W * HIDDEN]; // 40 MB: w_qkv^T, then w_o^T (K-permuted)

__device__ __forceinline__ float cvt_tf32(float x) {
    uint32_t u;
    asm("cvt.rna.tf32.f32 %0, %1;" : "=r"(u) : "f"(x));
    return __uint_as_float(u);
}
__device__ __forceinline__ uint32_t smem_u32(const void* p) {
    uint32_t a;
    asm("{ .reg .u64 t; cvta.to.shared.u64 t, %1; cvt.u32.u64 %0, t; }"
        : "=r"(a) : "l"(p));
    return a;
}
#define CP_ASYNC16(dst_u32, src_ptr) \
    asm volatile("cp.async.ca.shared.global [%0], [%1], 16;" \
                 :: "r"(dst_u32), "l"(src_ptr))
#define CP_COMMIT() asm volatile("cp.async.commit_group;")
#define CP_WAIT0()  asm volatile("cp.async.wait_group 0;")
#define CP_WAIT1()  asm volatile("cp.async.wait_group 1;")

__device__ __forceinline__ void mma_tf32(float c[4], const uint32_t a[4], const uint32_t b[2]) {
    asm volatile("mma.sync.aligned.m16n8k8.row.col.f32.tf32.tf32.f32 "
                 "{%0,%1,%2,%3}, {%4,%5,%6,%7}, {%8,%9}, {%0,%1,%2,%3};"
                 : "+f"(c[0]), "+f"(c[1]), "+f"(c[2]), "+f"(c[3])
                 : "r"(a[0]), "r"(a[1]), "r"(a[2]), "r"(a[3]),
                   "r"(b[0]), "r"(b[1]));
}

// =====================================================================
// Transpose + tf32 round (weights), K-permuted output columns
// =====================================================================
__global__ __launch_bounds__(256)
void transpose_cvt(const float* __restrict__ in, float* __restrict__ out, int R, int C)
{
    __shared__ float t[32][33];
    int x  = blockIdx.x * 32 + threadIdx.x;
    int y0 = blockIdx.y * 32;
    #pragma unroll
    for (int j = threadIdx.y; j < 32; j += 8)
        t[j][threadIdx.x] = in[(size_t)(y0 + j) * C + x];
    __syncthreads();
    int xl = threadIdx.x & 7;
    int xp = (xl < 4) ? 2 * xl : 2 * xl - 7;          // perm within 8-group
    int x2p = ((y0 + threadIdx.x) & ~7) + xp;         // permuted K column
    int y20 = blockIdx.x * 32;
    #pragma unroll
    for (int j = threadIdx.y; j < 32; j += 8)
        out[(size_t)(y20 + j) * R + x2p] = cvt_tf32(t[threadIdx.x][j]);
}

// =====================================================================
// tf32 rounding copy (hidden -> hid buffer), K-permuted (8 floats/thread)
// =====================================================================
__global__ __launch_bounds__(256)
void cvt32(const float* __restrict__ in, float* __restrict__ out)
{
    int i = (blockIdx.x * 256 + threadIdx.x) * 8;
    float4 u = *(const float4*)(in + i);
    float4 v = *(const float4*)(in + i + 4);
    // stored order = logical [0,4,1,5, 2,6,3,7]
    float4 oa = make_float4(cvt_tf32(u.x), cvt_tf32(v.x), cvt_tf32(u.y), cvt_tf32(v.y));
    float4 ob = make_float4(cvt_tf32(u.z), cvt_tf32(v.z), cvt_tf32(u.w), cvt_tf32(v.w));
    *(float4*)(out + i)     = oa;
    *(float4*)(out + i + 4) = ob;
}

// =====================================================================
// Shared GEMM mainloop: 2-stage double buffer, BK=32, float2 frag loads
// =====================================================================
#define GS_ROW 36                      // 32 floats + 4 pad
#define GS_BUF (128 * GS_ROW)          // 4608 floats per buffer
#define GEMM_SMEM (4 * GS_BUF * 4)     // 73728 B

#define GEMM_PREFETCH(bofs_, off_)                                          \
    {                                                                       \
        CP_ASYNC16(s_as + (bofs_) + so0,      Ar0 + (off_));                \
        CP_ASYNC16(s_as + (bofs_) + so0 + 64, Ar0 + (off_) + 16);           \
        CP_ASYNC16(s_as + (bofs_) + so1,      Ar1 + (off_));                \
        CP_ASYNC16(s_as + (bofs_) + so1 + 64, Ar1 + (off_) + 16);           \
        CP_ASYNC16(s_bs + (bofs_) + so0,      Br0 + (off_));                \
        CP_ASYNC16(s_bs + (bofs_) + so0 + 64, Br0 + (off_) + 16);           \
        CP_ASYNC16(s_bs + (bofs_) + so1,      Br1 + (off_));                \
        CP_ASYNC16(s_bs + (bofs_) + so1 + 64, Br1 + (off_) + 16);           \
        CP_COMMIT();                                                        \
    }

#define GEMM_MAINLOOP(A, Bt, Kdim)                                          \
    float* As = sm;                                                         \
    float* Bs = sm + 2 * GS_BUF;                                            \
    const uint32_t s_as = smem_u32(As);                                     \
    const uint32_t s_bs = smem_u32(Bs);                                     \
    const int r   = tid >> 2;                                               \
    const int seg = tid & 3;                                                \
    const float* Ar0 = (A)  + (size_t)(m0 + r)      * (Kdim) + seg * 4;     \
    const float* Ar1 = (A)  + (size_t)(m0 + r + 64) * (Kdim) + seg * 4;     \
    const float* Br0 = (Bt) + (size_t)(n0 + r)      * (Kdim) + seg * 4;     \
    const float* Br1 = (Bt) + (size_t)(n0 + r + 64) * (Kdim) + seg * 4;     \
    const uint32_t so0 = (uint32_t)(r * GS_ROW + seg * 4) * 4;              \
    const uint32_t so1 = (uint32_t)((r + 64) * GS_ROW + seg * 4) * 4;       \
    GEMM_PREFETCH(0u, 0)                                                    \
    const int nk = (Kdim) >> 5;                                             \
    for (int i = 0; i < nk; i++) {                                          \
        const int cur = i & 1;                                              \
        const bool more = (i + 1 < nk);                                     \
        if (more) {                                                         \
            const uint32_t bofs = (uint32_t)(((i + 1) & 1) * GS_BUF) * 4;   \
            const int off = (i + 1) << 5;                                   \
            GEMM_PREFETCH(bofs, off)                                        \
            CP_WAIT1();                                                     \
        } else {                                                            \
            CP_WAIT0();                                                     \
        }                                                                   \
        __syncthreads();                                                    \
        const float* Ab = As + cur * GS_BUF;                                \
        const float* Bb = Bs + cur * GS_BUF;                                \
        _Pragma("unroll")                                                   \
        for (int kk = 0; kk < 4; kk++) {                                    \
            const int ko = kk * 8 + 2 * tg;   /* permuted: k=tg,tg+4 adj */ \
            uint32_t af[2][4];                                              \
            _Pragma("unroll")                                               \
            for (int mt = 0; mt < 2; mt++) {                                \
                const float* base = Ab + (wm + mt * 16 + gq) * GS_ROW + ko; \
                float2 va = *(const float2*)base;                           \
                float2 vb = *(const float2*)(base + 8 * GS_ROW);            \
                af[mt][0] = __float_as_uint(va.x);                          \
                af[mt][2] = __float_as_uint(va.y);                          \
                af[mt][1] = __float_as_uint(vb.x);                          \
                af[mt][3] = __float_as_uint(vb.y);                          \
            }                                                               \
            uint32_t bf[8][2];                                              \
            _Pragma("unroll")                                               \
            for (int nt = 0; nt < 8; nt++) {                                \
                float2 vc = *(const float2*)(Bb + (wn + nt * 8 + gq) * GS_ROW + ko); \
                bf[nt][0] = __float_as_uint(vc.x);                          \
                bf[nt][1] = __float_as_uint(vc.y);                          \
            }                                                               \
            _Pragma("unroll")                                               \
            for (int mt = 0; mt < 2; mt++)                                  \
                _Pragma("unroll")                                           \
                for (int nt = 0; nt < 8; nt++)                              \
                    mma_tf32(c[mt][nt], af[mt], bf[nt]);                    \
        }                                                                   \
        __syncthreads();                                                    \
    }

// =====================================================================
// Plain tf32 GEMM (O-projection): C = A @ Bt^T  (A,Bt K-permuted)
// =====================================================================
__global__ __launch_bounds__(256, 2)
void tf32_gemm(const float* __restrict__ A, const float* __restrict__ Bt,
               float* __restrict__ C, int M, int N, int K)
{
    extern __shared__ float sm[];
    const int tid = threadIdx.x;
    const int m0 = blockIdx.y * 128;
    const int n0 = blockIdx.x * 128;
    const int wid  = tid >> 5;
    const int lane = tid & 31;
    const int wm = (wid >> 1) * 32;
    const int wn = (wid & 1) * 64;
    const int gq = lane >> 2;
    const int tg = lane & 3;

    float c[2][8][4] = {};
    GEMM_MAINLOOP(A, Bt, K)

    #pragma unroll
    for (int mt = 0; mt < 2; mt++) {
        const int row = m0 + wm + mt * 16 + gq;
        #pragma unroll
        for (int nt = 0; nt < 8; nt++) {
            const int col = n0 + wn + nt * 8 + tg * 2;
            *(float2*)(C + (size_t)row * N + col)       = make_float2(c[mt][nt][0], c[mt][nt][1]);
            *(float2*)(C + (size_t)(row + 8) * N + col) = make_float2(c[mt][nt][2], c[mt][nt][3]);
        }
    }
}

// =====================================================================
// Fused QKV GEMM: tile = one head. (A,Bt K-permuted inputs; outputs
// g_qn/g_kn/g_vt in LOGICAL layout — N dim is not permuted.)
// =====================================================================
__global__ __launch_bounds__(256, 2)
void tf32_gemm_qkv(const float* __restrict__ A, const float* __restrict__ Bt,
                   const int* __restrict__ positions,
                   const float* __restrict__ qw, const float* __restrict__ kw)
{
    extern __shared__ float sm[];
    const int tid = threadIdx.x;
    const int m0 = blockIdx.y * 128;
    const int hb = blockIdx.x;            // head block 0..39
    const int n0 = hb * 128;
    const int wid  = tid >> 5;
    const int lane = tid & 31;
    const int wm = (wid >> 1) * 32;
    const int wn = (wid & 1) * 64;
    const int gq = lane >> 2;
    const int tg = lane & 3;

    float c[2][8][4] = {};
    GEMM_MAINLOOP(A, Bt, HIDDEN)

    // ---------------- fused epilogue ----------------
    float* xb  = sm;              // [128][69] exchange / transpose buffer
    float* ssm = sm + 128 * 69;   // [128][2] sumsq partials

    int trow[4];                  // rows held by this thread (j = mt*2 + half)
    #pragma unroll
    for (int j = 0; j < 4; j++) trow[j] = wm + (j >> 1) * 16 + (j & 1) * 8 + gq;

    if (hb < 36) {
        // ---- sumsq per row (quad shfl + cross-warp smem) ----
        float p4[4];
        #pragma unroll
        for (int j = 0; j < 4; j++) {
            int mt = j >> 1, hf = (j & 1) * 2;
            float p = 0.f;
            #pragma unroll
            for (int nt = 0; nt < 8; nt++) {
                float v0 = c[mt][nt][hf], v1 = c[mt][nt][hf + 1];
                p += v0 * v0 + v1 * v1;
            }
            p += __shfl_xor_sync(0xffffffff, p, 1);
            p += __shfl_xor_sync(0xffffffff, p, 2);
            p4[j] = p;
        }
        if (tg == 0) {
            #pragma unroll
            for (int j = 0; j < 4; j++)
                ssm[trow[j] * 2 + (wid & 1)] = p4[j];
        }
        __syncthreads();
        float rinv[4];
        int pos4[4];
        #pragma unroll
        for (int j = 0; j < 4; j++) {
            rinv[j] = rsqrtf((ssm[trow[j] * 2] + ssm[trow[j] * 2 + 1]) * (1.0f / 128.0f) + EPS);
            pos4[j] = positions[m0 + trow[j]];
        }
        // ---- normalize in place ----
        const float* wv = (hb < 32) ? qw : kw;
        #pragma unroll
        for (int nt = 0; nt < 8; nt++) {
            int col = wn + nt * 8 + tg * 2;
            float w0 = wv[col], w1 = wv[col + 1];
            #pragma unroll
            for (int mt = 0; mt < 2; mt++) {
                c[mt][nt][0] *= rinv[mt * 2] * w0;
                c[mt][nt][1] *= rinv[mt * 2] * w1;
                c[mt][nt][2] *= rinv[mt * 2 + 1] * w0;
                c[mt][nt][3] *= rinv[mt * 2 + 1] * w1;
            }
        }
        float* gout = (hb < 32) ? g_qn : g_kn;
        const size_t rstride = (hb < 32) ? (size_t)(NH * D) : (size_t)(NKV * D);
        const size_t hofs = (hb < 32) ? (size_t)hb * D : (size_t)(hb - 32) * D;

        // ---- rope: upper-half warps publish x2 ----
        if (wid & 1) {
            #pragma unroll
            for (int nt = 0; nt < 8; nt++) {
                int d = nt * 8 + tg * 2;   // col - 64
                #pragma unroll
                for (int j = 0; j < 4; j++) {
                    int mt = j >> 1, hf = (j & 1) * 2;
                    xb[trow[j] * 69 + d]     = c[mt][nt][hf];
                    xb[trow[j] * 69 + d + 1] = c[mt][nt][hf + 1];
                }
            }
        }
        __syncthreads();
        // ---- lower-half warps compute both rotated halves ----
        if (!(wid & 1)) {
            #pragma unroll
            for (int nt = 0; nt < 8; nt++) {
                int d0 = nt * 8 + tg * 2;
                float invf0 = exp2f((float)d0 * -0.31143075889569023f);
                float invf1 = exp2f((float)(d0 + 1) * -0.31143075889569023f);
                #pragma unroll
                for (int j = 0; j < 4; j++) {
                    int mt = j >> 1, hf = (j & 1) * 2;
                    float x1a = c[mt][nt][hf], x1b = c[mt][nt][hf + 1];
                    float x2a = xb[trow[j] * 69 + d0];
                    float x2b = xb[trow[j] * 69 + d0 + 1];
                    float pos = (float)pos4[j];
                    float sa, ca, sb, cb;
                    sincosf(pos * invf0, &sa, &ca);
                    sincosf(pos * invf1, &sb, &cb);
                    float o1a = x1a * ca - x2a * sa;
                    float o1b = x1b * cb - x2b * sb;
                    float o2a = x2a * ca + x1a * sa;
                    float o2b = x2b * cb + x1b * sb;
                    size_t base = (size_t)(m0 + trow[j]) * rstride + hofs + d0;
                    *(float2*)&gout[base] = make_float2(cvt_tf32(o1a), cvt_tf32(o1b));
                    xb[trow[j] * 69 + d0]     = cvt_tf32(o2a);
                    xb[trow[j] * 69 + d0 + 1] = cvt_tf32(o2b);
                }
            }
        }
        __syncthreads();
        // ---- upper-half warps store o2 ----
        if (wid & 1) {
            #pragma unroll
            for (int nt = 0; nt < 8; nt++) {
                int d0 = nt * 8 + tg * 2;
                #pragma unroll
                for (int j = 0; j < 4; j++) {
                    float o2a = xb[trow[j] * 69 + d0];
                    float o2b = xb[trow[j] * 69 + d0 + 1];
                    size_t base = (size_t)(m0 + trow[j]) * rstride + hofs + 64 + d0;
                    *(float2*)&gout[base] = make_float2(o2a, o2b);
                }
            }
        }
    } else {
        // ---- V: tf32 + transpose to g_vt[kvh][d][t] ----
        const int kvh = hb - 36;
        #pragma unroll
        for (int rr2 = 0; rr2 < 2; rr2++) {
            __syncthreads();
            if ((wid & 1) == rr2) {
                #pragma unroll
                for (int nt = 0; nt < 8; nt++) {
                    int d = nt * 8 + tg * 2;   // col - 64*rr2
                    #pragma unroll
                    for (int j = 0; j < 4; j++) {
                        int mt = j >> 1, hf = (j & 1) * 2;
                        xb[trow[j] * 69 + d]     = cvt_tf32(c[mt][nt][hf]);
                        xb[trow[j] * 69 + d + 1] = cvt_tf32(c[mt][nt][hf + 1]);
                    }
                }
            }
            __syncthreads();
            int dp = tid >> 2;              // 0..63
            int t0 = (tid & 3) * 32;
            float* orow = g_vt + ((size_t)kvh * D + 64 * rr2 + dp) * T + m0 + t0;
            #pragma unroll
            for (int u = 0; u < 8; u++) {
                float4 vv;
                vv.x = xb[(t0 + u * 4 + 0) * 69 + dp];
                vv.y = xb[(t0 + u * 4 + 1) * 69 + dp];
                vv.z = xb[(t0 + u * 4 + 2) * 69 + dp];
                vv.w = xb[(t0 + u * 4 + 3) * 69 + dp];
                *(float4*)orow = vv;
                orow += 4;
            }
        }
    }
}

// =====================================================================
// Sliding-window flash attention — 4 barriers/iter, register m/l state
// g_ao output is K-PERMUTED (feeds O-proj GEMM A operand).
// grid (T/64, NH), 256 threads, 2 CTAs/SM (87 KB smem)
// =====================================================================
#define AO_QS 0
#define AO_KV 8448
#define AO_PS 17152
#define AO_PM 21504
#define AO_SU 21632
#define ATTN_SMEM_FLOATS 21760
#define ATTN_SMEM_BYTES (ATTN_SMEM_FLOATS * 4)   // 87040

__global__ __launch_bounds__(256, 2)
void attn_kernel()
{
    extern __shared__ float sm[];
    float* Qs   = sm + AO_QS;
    float* Ks   = sm + AO_KV;      // K view  [64][132]
    float* Vt   = sm + AO_KV;      // V view  [128][68]
    float* Ps   = sm + AO_PS;      // [64][68]
    float* pm   = sm + AO_PM;      // [2][64]
    float* psum = sm + AO_SU;      // [2][64]
    const uint32_t s_qs = smem_u32(Qs);
    const uint32_t s_kv = smem_u32(Ks);

    const int tid  = threadIdx.x;
    const int wid  = tid >> 5;
    const int lane = tid & 31;
    const int gq = lane >> 2;
    const int tg = lane & 3;
    const int wm = (wid & 3) * 16;
    const int wn = wid >> 2;
    const int h  = blockIdx.y;
    const int kvh = h >> 3;
    const int qs = blockIdx.x * 64;
    const int row0 = wm + gq;        // this thread's rows
    const int row1 = row0 + 8;

    // Q tile via cp.async
    #pragma unroll
    for (int i = 0; i < 8; i++) {
        int f = tid + i * 256;
        int row = f >> 5;
        int c4  = (f & 31) << 2;
        CP_ASYNC16(s_qs + (uint32_t)(row * 132 + c4) * 4,
                   g_qn + (((size_t)(qs + row)) * NH + h) * D + c4);
    }
    CP_COMMIT();

    float O[8][4] = {};
    float mo0 = -1e30f, mo1 = -1e30f, l0 = 0.f, l1 = 0.f;

    const int kt_lo = max(0, qs - (WINDOW - 1)) >> 6;
    const int kt_hi = (qs + 63) >> 6;

    for (int kt = kt_lo; kt <= kt_hi; kt++) {
        const int ks = kt * 64;
        __syncthreads();               // A: prev PV reads done -> KV/Ps free

        // K tile
        #pragma unroll
        for (int i = 0; i < 8; i++) {
            int f = tid + i * 256;
            int row = f >> 5;
            int c4  = (f & 31) << 2;
            CP_ASYNC16(s_kv + (uint32_t)(row * 132 + c4) * 4,
                       g_kn + (((size_t)(ks + row)) * NKV + kvh) * D + c4);
        }
        CP_COMMIT();
        CP_WAIT0();
        __syncthreads();               // B: K (and Q on first iter) visible

        // ---- S = Q @ K^T ----
        float s[4][4] = {};
        #pragma unroll
        for (int kc = 0; kc < 16; kc++) {
            uint32_t a[4];
            const float* qb = Qs + row0 * 132 + kc * 8 + tg;
            a[0] = __float_as_uint(qb[0]);
            a[1] = __float_as_uint(qb[8 * 132]);
            a[2] = __float_as_uint(qb[4]);
            a[3] = __float_as_uint(qb[8 * 132 + 4]);
            #pragma unroll
            for (int nt = 0; nt < 4; nt++) {
                uint32_t b[2];
                const float* kb = Ks + (wn * 32 + nt * 8 + gq) * 132 + kc * 8 + tg;
                b[0] = __float_as_uint(kb[0]);
                b[1] = __float_as_uint(kb[4]);
                mma_tf32(s[nt], a, b);
            }
        }

        // ---- mask + scale ----
        const int rg0 = qs + row0;
        const int rg1 = rg0 + 8;
        #pragma unroll
        for (int nt = 0; nt < 4; nt++) {
            int cl = ks + wn * 32 + nt * 8 + 2 * tg;
            #pragma unroll
            for (int cc = 0; cc < 4; cc++) {
                int row = (cc < 2) ? rg0 : rg1;
                int col = cl + (cc & 1);
                bool ok = (col <= row) && (row - col < WINDOW);
                s[nt][cc] = ok ? s[nt][cc] * ATT_SCALE : -1e30f;
            }
        }

        // ---- row max ----
        float m0v = -1e30f, m1v = -1e30f;
        #pragma unroll
        for (int nt = 0; nt < 4; nt++) {
            m0v = fmaxf(m0v, fmaxf(s[nt][0], s[nt][1]));
            m1v = fmaxf(m1v, fmaxf(s[nt][2], s[nt][3]));
        }
        m0v = fmaxf(m0v, __shfl_xor_sync(0xffffffff, m0v, 1));
        m0v = fmaxf(m0v, __shfl_xor_sync(0xffffffff, m0v, 2));
        m1v = fmaxf(m1v, __shfl_xor_sync(0xffffffff, m1v, 1));
        m1v = fmaxf(m1v, __shfl_xor_sync(0xffffffff, m1v, 2));
        if (tg == 0) {
            pm[wn * 64 + row0] = m0v;
            pm[wn * 64 + row1] = m1v;
        }
        __syncthreads();               // C: pm visible, K reads done

        // V tile into SAME buffer (K dead)
        #pragma unroll
        for (int i = 0; i < 8; i++) {
            int f = tid + i * 256;
            int d = f >> 4;
            int j4 = (f & 15) << 2;
            CP_ASYNC16(s_kv + (uint32_t)(d * 68 + j4) * 4,
                       g_vt + ((size_t)kvh * D + d) * T + ks + j4);
        }
        CP_COMMIT();

        // ---- softmax with register state ----
        const float mn0 = fmaxf(mo0, fmaxf(pm[row0], pm[64 + row0]));
        const float mn1 = fmaxf(mo1, fmaxf(pm[row1], pm[64 + row1]));
        float sum0 = 0.f, sum1 = 0.f;
        #pragma unroll
        for (int nt = 0; nt < 4; nt++) {
            float p0 = (s[nt][0] > -1e29f) ? __expf(s[nt][0] - mn0) : 0.f;
            float p1 = (s[nt][1] > -1e29f) ? __expf(s[nt][1] - mn0) : 0.f;
            float p2 = (s[nt][2] > -1e29f) ? __expf(s[nt][2] - mn1) : 0.f;
            float p3 = (s[nt][3] > -1e29f) ? __expf(s[nt][3] - mn1) : 0.f;
            sum0 += p0 + p1;
            sum1 += p2 + p3;
            int cofs = wn * 32 + nt * 8 + 2 * tg;
            *(float2*)&Ps[row0 * 68 + cofs] = make_float2(cvt_tf32(p0), cvt_tf32(p1));
            *(float2*)&Ps[row1 * 68 + cofs] = make_float2(cvt_tf32(p2), cvt_tf32(p3));
        }
        sum0 += __shfl_xor_sync(0xffffffff, sum0, 1);
        sum0 += __shfl_xor_sync(0xffffffff, sum0, 2);
        sum1 += __shfl_xor_sync(0xffffffff, sum1, 1);
        sum1 += __shfl_xor_sync(0xffffffff, sum1, 2);
        if (tg == 0) {
            psum[wn * 64 + row0] = sum0;
            psum[wn * 64 + row1] = sum1;
        }
        const float a0 = __expf(mo0 - mn0);
        const float a1 = __expf(mo1 - mn1);
        mo0 = mn0; mo1 = mn1;
        CP_WAIT0();                    // this thread's V copies done
        __syncthreads();               // D: psum + Ps + V all visible

        l0 = l0 * a0 + psum[row0] + psum[64 + row0];
        l1 = l1 * a1 + psum[row1] + psum[64 + row1];

        // ---- O rescale + PV ----
        #pragma unroll
        for (int nt = 0; nt < 8; nt++) {
            O[nt][0] *= a0; O[nt][1] *= a0;
            O[nt][2] *= a1; O[nt][3] *= a1;
        }
        #pragma unroll
        for (int kc = 0; kc < 8; kc++) {
            uint32_t a[4];
            const float* pb = Ps + row0 * 68 + kc * 8 + tg;
            a[0] = __float_as_uint(pb[0]);
            a[1] = __float_as_uint(pb[8 * 68]);
            a[2] = __float_as_uint(pb[4]);
            a[3] = __float_as_uint(pb[8 * 68 + 4]);
            #pragma unroll
            for (int nt = 0; nt < 8; nt++) {
                uint32_t b[2];
                const float* vb = Vt + (wn * 64 + nt * 8 + gq) * 68 + kc * 8 + tg;
                b[0] = __float_as_uint(vb[0]);
                b[1] = __float_as_uint(vb[4]);
                mma_tf32(O[nt], a, b);
            }
        }
    }

    // ---- epilogue: normalize, tf32-round, K-PERMUTED scatter for O-gemm ----
    {
        const float li0 = 1.0f / l0;
        const float li1 = 1.0f / l1;
        const size_t b0 = (size_t)(qs + row0) * (NH * D) + h * D;
        const size_t b1 = b0 + 8 * (size_t)(NH * D);
        // logical cols 2tg, 2tg+1 within each 8-group -> permuted positions
        const int p0 = (tg < 2) ? 4 * tg     : 4 * tg - 7;
        const int p1 = (tg < 2) ? 4 * tg + 2 : 4 * tg - 5;
        #pragma unroll
        for (int nt = 0; nt < 8; nt++) {
            int gb = wn * 64 + nt * 8;
            g_ao[b0 + gb + p0] = cvt_tf32(O[nt][0] * li0);
            g_ao[b0 + gb + p1] = cvt_tf32(O[nt][1] * li0);
            g_ao[b1 + gb + p0] = cvt_tf32(O[nt][2] * li1);
            g_ao[b1 + gb + p1] = cvt_tf32(O[nt][3] * li1);
        }
    }
}

// =====================================================================
// launch — attn at launch index 3 so ncu's fixed sample captures it
// =====================================================================
extern "C" void kernel_launch(void* const* d_in, const int* in_sizes, int n_in,
                              void* d_out, int out_size)
{
    const int*   positions = (const int*)  d_in[0];
    const float* hidden    = (const float*)d_in[1];
    const float* w_qkv     = (const float*)d_in[2];
    const float* w_o       = (const float*)d_in[3];
    const float* qw        = (const float*)d_in[4];
    const float* kw        = (const float*)d_in[5];
    float*       out       = (float*)d_out;

    float *ao, *wT;
    cudaGetSymbolAddress((void**)&ao, g_ao);
    cudaGetSymbolAddress((void**)&wT, g_wT);
    float* hid = ao;   // alias: hid dead before attention writes g_ao

    cudaFuncSetAttribute(tf32_gemm, cudaFuncAttributeMaxDynamicSharedMemorySize, GEMM_SMEM);
    cudaFuncSetAttribute(tf32_gemm_qkv, cudaFuncAttributeMaxDynamicSharedMemorySize, GEMM_SMEM);
    cudaFuncSetAttribute(attn_kernel, cudaFuncAttributeMaxDynamicSharedMemorySize, ATTN_SMEM_BYTES);

    // 0) w_qkv transpose (K-permuted) + hidden tf32 rounding (K-permuted)
    transpose_cvt<<<dim3(QKV_W / 32, HIDDEN / 32), dim3(32, 8)>>>(w_qkv, wT, HIDDEN, QKV_W);   // idx 0
    cvt32<<<(T * HIDDEN) / 2048, 256>>>(hidden, hid);                                          // idx 1

    // 1) fused QKV projection + rmsnorm + rope + V transpose
    tf32_gemm_qkv<<<dim3(QKV_W / 128, T / 128), 256, GEMM_SMEM>>>(hid, wT, positions, qw, kw); // idx 2

    // 2) sliding-window attention (index 3 -> gets profiled)
    attn_kernel<<<dim3(T / 64, NH), 256, ATTN_SMEM_BYTES>>>();                                 // idx 3

    // 3) w_o transpose (K-permuted; wT reusable after QKV gemm)
    transpose_cvt<<<dim3(HIDDEN / 32, (NH * D) / 32), dim3(32, 8)>>>(w_o, wT, NH * D, HIDDEN); // idx 4

    // 4) output projection
    tf32_gemm<<<dim3(HIDDEN / 128, T / 128), 256, GEMM_SMEM>>>(ao, wT, out, T, HIDDEN, NH * D); // idx 5
}